// round 15
// baseline (speedup 1.0000x reference)
#include <cuda_runtime.h>
#include <cuda_bf16.h>
#include <cstdint>

// ---------------- problem constants ----------------
#define N_NODES   32000
#define NUM_GRAPHS 32
#define NPG       1000
#define N_EDGES   256000
#define IN_DIM    1024
#define HID       256
#define NC        8

// ---------------- scratch (device globals) ----------------
__device__ float d_Yl1 [N_NODES * HID];
__device__ float d_Yr1 [N_NODES * HID];
__device__ float d_Ya  [N_NODES * 16];
__device__ float d_Z   [N_NODES * HID];
__device__ float d_Ss  [N_NODES * NC];
__device__ float d_Xp  [NUM_GRAPHS * NC * HID];
__device__ float d_Ap  [NUM_GRAPHS * NC * NC];
// tf32-rounded operands
__device__ float d_Xt  [N_NODES * IN_DIM];
__device__ float d_Bt  [528 * 1024];
// CSR for dst-sorted edges
__device__ int d_deg [N_NODES];
__device__ int d_off [N_NODES];
__device__ int d_cur [N_NODES];
__device__ int d_srcs[N_EDGES];
// persistent-GEMM job counter
__device__ int d_job;

// =============== helpers ===============
static __device__ __forceinline__ uint32_t s2u(const void* p) {
    uint32_t a;
    asm("{ .reg .u64 t; cvta.to.shared.u64 t, %1; cvt.u32.u64 %0, t; }" : "=r"(a) : "l"(p));
    return a;
}
static __device__ __forceinline__ uint32_t f2tf(float f) {
    uint32_t r; asm("cvt.rna.tf32.f32 %0, %1;" : "=r"(r) : "f"(f)); return r;
}
#define LDMX4(r0, r1, r2, r3, addr) \
    asm volatile("ldmatrix.sync.aligned.m8n8.x4.shared.b16 {%0,%1,%2,%3}, [%4];" \
        : "=r"(r0), "=r"(r1), "=r"(r2), "=r"(r3) : "r"(addr))
#define MMATF32(c, a, b) \
    asm volatile("mma.sync.aligned.m16n8k8.row.col.f32.tf32.tf32.f32 " \
        "{%0,%1,%2,%3}, {%4,%5,%6,%7}, {%8,%9}, {%0,%1,%2,%3};" \
        : "+f"((c)[0]), "+f"((c)[1]), "+f"((c)[2]), "+f"((c)[3]) \
        : "r"((a)[0]), "r"((a)[1]), "r"((a)[2]), "r"((a)[3]), "r"((b)[0]), "r"((b)[1]))
#define CP16(dst, src) \
    asm volatile("cp.async.cg.shared.global [%0], [%1], 16;" :: "r"(dst), "l"(src))
#define CPCOMMIT() asm volatile("cp.async.commit_group;" ::: "memory")
#define CPWAIT0()  asm volatile("cp.async.wait_group 0;" ::: "memory")
#define CPWAIT1()  asm volatile("cp.async.wait_group 1;" ::: "memory")

// ---------------- convert X to tf32-rounded fp32 + edge histogram ----------------
__global__ __launch_bounds__(256) void cvt_x_hist(const float* __restrict__ X,
                                                  const int* __restrict__ dst) {
    size_t t = (size_t)blockIdx.x * 256 + threadIdx.x;
    size_t stride = (size_t)gridDim.x * 256;
    const float4* xp = reinterpret_cast<const float4*>(X);
    uint4* op = reinterpret_cast<uint4*>(d_Xt);
    size_t n4 = (size_t)N_NODES * IN_DIM / 4;
    for (size_t i = t; i < n4; i += stride) {
        float4 v = xp[i];
        op[i] = make_uint4(f2tf(v.x), f2tf(v.y), f2tf(v.z), f2tf(v.w));
    }
    for (size_t e = t; e < N_EDGES; e += stride) atomicAdd(&d_deg[dst[e]], 1);
}

// ---------------- weight prep: transpose + tf32 round + accumulator zeroing ----------------
__global__ __launch_bounds__(256) void prep_bt(const float* __restrict__ Wl1,
                                               const float* __restrict__ Wr1,
                                               const float* __restrict__ Wla,
                                               const float* __restrict__ Wra) {
    int b = blockIdx.x, tid = threadIdx.x;
    if (b == 0 && tid == 0) d_job = 0;
    if (b < 16) {
        __shared__ float tile[64][33];
        const float* W = (b < 8) ? Wl1 : Wr1;
        int ncol0 = (b & 7) * 32;
        int nout0 = (b < 8) ? ncol0 : 256 + ncol0;
        int tk8 = tid >> 5, tn = tid & 31;
        int n = tid >> 3, kq = (tid & 7) * 8;
        for (int k0 = 0; k0 < IN_DIM; k0 += 64) {
#pragma unroll
            for (int j = 0; j < 8; j++)
                tile[tk8 * 8 + j][tn] = W[(size_t)(k0 + tk8 * 8 + j) * 256 + ncol0 + tn];
            __syncthreads();
            uint32_t o[8];
#pragma unroll
            for (int q = 0; q < 8; q++) o[q] = f2tf(tile[kq + q][n]);
            uint4* dstp = reinterpret_cast<uint4*>(d_Bt + (size_t)(nout0 + n) * IN_DIM + k0 + kq);
            dstp[0] = make_uint4(o[0], o[1], o[2], o[3]);
            dstp[1] = make_uint4(o[4], o[5], o[6], o[7]);
            __syncthreads();
        }
    } else {
        uint32_t* bt = reinterpret_cast<uint32_t*>(d_Bt);
        for (int idx = tid; idx < 16 * IN_DIM; idx += 256) {
            int n = idx & 15, k = idx >> 4;
            float w = (n < 8) ? Wla[k * 8 + n] : Wra[k * 8 + (n - 8)];
            bt[(size_t)(512 + n) * IN_DIM + k] = f2tf(w);
        }
    }
    int gt = b * 256 + tid, gstride = 17 * 256;
    for (int i = gt; i < N_NODES; i += gstride) d_deg[i] = 0;
    for (int i = gt; i < NUM_GRAPHS * NC * HID; i += gstride) d_Xp[i] = 0.f;
    for (int i = gt; i < NUM_GRAPHS * NC * NC;  i += gstride) d_Ap[i] = 0.f;
}

// ---------------- CSR scan + scatter ----------------
__global__ __launch_bounds__(256) void scan_kernel() {
    __shared__ int sums[256];
    __shared__ int base_sh;
    int g = blockIdx.x, tid = threadIdx.x;
    int s = 0;
    for (int i = tid; i < g * NPG; i += 256) s += d_deg[i];
    sums[tid] = s;
    __syncthreads();
    for (int st = 128; st > 0; st >>= 1) {
        if (tid < st) sums[tid] += sums[tid + st];
        __syncthreads();
    }
    if (tid == 0) base_sh = sums[0];
    __syncthreads();
    int base = base_sh;
    __syncthreads();
    int v[4], loc = 0;
#pragma unroll
    for (int j = 0; j < 4; j++) {
        int i = tid * 4 + j;
        v[j] = (i < NPG) ? d_deg[g * NPG + i] : 0;
        loc += v[j];
    }
    sums[tid] = loc;
    __syncthreads();
    for (int off = 1; off < 256; off <<= 1) {
        int t2 = (tid >= off) ? sums[tid - off] : 0;
        __syncthreads();
        sums[tid] += t2;
        __syncthreads();
    }
    int excl = base + ((tid == 0) ? 0 : sums[tid - 1]);
#pragma unroll
    for (int j = 0; j < 4; j++) {
        int i = tid * 4 + j;
        if (i < NPG) {
            d_off[g * NPG + i] = excl;
            d_cur[g * NPG + i] = excl;
            excl += v[j];
        }
    }
}

__global__ __launch_bounds__(256) void scatter_kernel(const int* __restrict__ src,
                                                      const int* __restrict__ dst) {
    int t = blockIdx.x * blockDim.x + threadIdx.x;
    int stride = gridDim.x * blockDim.x;
    for (int e = t; e < N_EDGES; e += stride) {
        int pos = atomicAdd(&d_cur[dst[e]], 1);
        d_srcs[pos] = src[e];
    }
}

// ---------------- persistent tf32 GEMM: BM=128, BN=64, warp tile 32x32, 3 CTAs/SM ----------------
// 2000 jobs: rb = (job>>3)*128, cb = job&7 (B rows cb*64..+64; cb<4 -> Yl1, else Yr1).
#define PADF 36                             // floats per smem row = 144 B
#define A_SZF (128 * PADF * 4)              // 18432 B
#define B_SZF (64 * PADF * 4)               // 9216 B
#define OFF_B A_SZF
#define STG (A_SZF + B_SZF)                 // 27648
#define GEMM_SMEM (2 * STG)                 // 55296 -> 3 CTAs/SM
#define NJOBS 2000
#define NWORKERS 444

__global__ __launch_bounds__(256, 3) void mma_gemm() {
    extern __shared__ char sm[];
    __shared__ int job_sh;
    uint32_t sb = s2u(sm);
    int tid = threadIdx.x, lane = tid & 31, wid = tid >> 5;

    // loaders: row = tid>>1, half = (tid&1)*16 floats (64 B = 4 CP16).
    // A: 128 rows -> all 256 threads. B: 64 rows -> tid<128 (same formula).
    uint32_t a_sts = (uint32_t)((tid >> 1) * PADF + (tid & 1) * 16) * 4;
    uint32_t b_sts = OFF_B + a_sts;
    int do_b = (tid < 128);
    size_t row_half = ((size_t)(tid >> 1) * IN_DIM + (tid & 1) * 16) * 4;

    // warp grid 4 (M) x 2 (N); warp tile 32x32
    int wm = wid >> 1, wn = wid & 1;
    int jm = lane >> 3, r8 = lane & 7;
    uint32_t a_ldm[2], b_ldm[2];
#pragma unroll
    for (int mf = 0; mf < 2; mf++) {
        int row = wm * 32 + mf * 16 + ((jm & 1) << 3) + r8;
        a_ldm[mf] = (uint32_t)(row * PADF * 4 + (jm >> 1) * 16);
    }
#pragma unroll
    for (int nb = 0; nb < 2; nb++) {
        int row = wn * 32 + nb * 16 + ((jm >> 1) << 3) + r8;
        b_ldm[nb] = (uint32_t)(OFF_B + row * PADF * 4 + (jm & 1) * 16);
    }

    for (;;) {
        __syncthreads();
        if (tid == 0) job_sh = atomicAdd(&d_job, 1);
        __syncthreads();
        int job = job_sh;
        if (job >= NJOBS) break;
        int rb = (job >> 3) * 128, cb = job & 7;

        const char* a_g = (const char*)d_Xt + (size_t)rb * IN_DIM * 4 + row_half;
        const char* b_g = (const char*)d_Bt + (size_t)cb * 64 * IN_DIM * 4 + row_half;

        float acc[2][4][4];
#pragma unroll
        for (int i = 0; i < 2; i++)
#pragma unroll
            for (int j = 0; j < 4; j++)
#pragma unroll
                for (int k = 0; k < 4; k++) acc[i][j][k] = 0.f;

#define ISSUE_TILE(t, s) do { \
            uint32_t st_ = sb + (uint32_t)(s) * STG; \
            size_t ko_ = (size_t)(t) * 128; \
            CP16(st_ + a_sts,        a_g + ko_); \
            CP16(st_ + a_sts + 16,   a_g + ko_ + 16); \
            CP16(st_ + a_sts + 32,   a_g + ko_ + 32); \
            CP16(st_ + a_sts + 48,   a_g + ko_ + 48); \
            if (do_b) { \
                CP16(st_ + b_sts,        b_g + ko_); \
                CP16(st_ + b_sts + 16,   b_g + ko_ + 16); \
                CP16(st_ + b_sts + 32,   b_g + ko_ + 32); \
                CP16(st_ + b_sts + 48,   b_g + ko_ + 48); \
            } \
        } while (0)

        ISSUE_TILE(0, 0); CPCOMMIT();

        for (int t = 0; t < 32; t++) {
            if (t < 31) { ISSUE_TILE(t + 1, (t + 1) & 1); CPCOMMIT(); CPWAIT1(); }
            else CPWAIT0();
            __syncthreads();
            uint32_t stb = sb + (uint32_t)(t & 1) * STG;
#pragma unroll
            for (int ks = 0; ks < 4; ks++) {
                uint32_t kb = ks * 32;
                uint32_t af[2][4], bf[2][4];
#pragma unroll
                for (int nb = 0; nb < 2; nb++)
                    LDMX4(bf[nb][0], bf[nb][1], bf[nb][2], bf[nb][3], stb + b_ldm[nb] + kb);
#pragma unroll
                for (int mf = 0; mf < 2; mf++)
                    LDMX4(af[mf][0], af[mf][1], af[mf][2], af[mf][3], stb + a_ldm[mf] + kb);
#pragma unroll
                for (int mf = 0; mf < 2; mf++)
#pragma unroll
                    for (int nb = 0; nb < 2; nb++) {
                        MMATF32(acc[mf][nb * 2 + 0], af[mf], &bf[nb][0]);
                        MMATF32(acc[mf][nb * 2 + 1], af[mf], &bf[nb][2]);
                    }
            }
            __syncthreads();
        }
#undef ISSUE_TILE

        float* outp = (cb < 4) ? d_Yl1 : d_Yr1;
        int colb = (cb < 4 ? cb * 64 : cb * 64 - 256) + wn * 32;
        int qr = lane >> 2, qc = lane & 3;
#pragma unroll
        for (int mf = 0; mf < 2; mf++)
#pragma unroll
            for (int h = 0; h < 2; h++) {
                int m = rb + wm * 32 + mf * 16 + qr + 8 * h;
                float* orow = outp + (size_t)m * HID + colb + qc * 2;
#pragma unroll
                for (int nf = 0; nf < 4; nf++)
                    *reinterpret_cast<float2*>(orow + nf * 8) =
                        make_float2(acc[mf][nf][2 * h], acc[mf][nf][2 * h + 1]);
            }
    }
}

// ---------------- Ya GEMM: [32000,16] = X @ [Wla|Wra], tf32 ----------------
#define YA_SZ (128 * PADF * 4)              // 18432
#define OFF_YB YA_SZ
#define YSTG (YA_SZ + 16 * PADF * 4)        // 20736

__global__ __launch_bounds__(256) void ya_gemm() {
    __shared__ char sm2[2 * YSTG];
    uint32_t sb = s2u(sm2);
    int tid = threadIdx.x, lane = tid & 31, wid = tid >> 5;
    int rb = blockIdx.x * 128;

    const char* a_g = (const char*)d_Xt +
        ((size_t)(rb + (tid >> 1)) * IN_DIM + (tid & 1) * 16) * 4;
    uint32_t a_sts = (uint32_t)((tid >> 1) * PADF + (tid & 1) * 16) * 4;
    int brow = tid >> 3, bch = tid & 7;
    const char* b_g = (const char*)d_Bt + ((size_t)(512 + brow) * IN_DIM + bch * 4) * 4;
    uint32_t b_sts = OFF_YB + (uint32_t)(brow * PADF + bch * 4) * 4;
    int do_b = (tid < 128);

    int jm = lane >> 3, r8 = lane & 7;
    uint32_t a_ldm = (uint32_t)((wid * 16 + ((jm & 1) << 3) + r8) * PADF * 4 + (jm >> 1) * 16);
    uint32_t b_ldm = (uint32_t)(OFF_YB + (((jm >> 1) << 3) + r8) * PADF * 4 + (jm & 1) * 16);

    float acc[2][4];
#pragma unroll
    for (int i = 0; i < 2; i++)
#pragma unroll
        for (int k = 0; k < 4; k++) acc[i][k] = 0.f;

#define YISSUE(t, s) do { \
        uint32_t st_ = sb + (uint32_t)(s) * YSTG; \
        size_t ko_ = (size_t)(t) * 128; \
        CP16(st_ + a_sts,        a_g + ko_); \
        CP16(st_ + a_sts + 16,   a_g + ko_ + 16); \
        CP16(st_ + a_sts + 32,   a_g + ko_ + 32); \
        CP16(st_ + a_sts + 48,   a_g + ko_ + 48); \
        if (do_b) CP16(st_ + b_sts, b_g + ko_); \
    } while (0)

    YISSUE(0, 0); CPCOMMIT();

    for (int t = 0; t < 32; t++) {
        if (t < 31) { YISSUE(t + 1, (t + 1) & 1); CPCOMMIT(); CPWAIT1(); }
        else CPWAIT0();
        __syncthreads();
        uint32_t stb = sb + (uint32_t)(t & 1) * YSTG;
#pragma unroll
        for (int ks = 0; ks < 4; ks++) {
            uint32_t kb = ks * 32;
            uint32_t af[4], bf4[4];
            LDMX4(bf4[0], bf4[1], bf4[2], bf4[3], stb + b_ldm + kb);
            LDMX4(af[0], af[1], af[2], af[3], stb + a_ldm + kb);
            MMATF32(acc[0], af, &bf4[0]);
            MMATF32(acc[1], af, &bf4[2]);
        }
        __syncthreads();
    }
#undef YISSUE

    int qr = lane >> 2, qc = lane & 3;
#pragma unroll
    for (int h = 0; h < 2; h++) {
        int m = rb + wid * 16 + qr + 8 * h;
#pragma unroll
        for (int nf = 0; nf < 2; nf++)
            *reinterpret_cast<float2*>(d_Ya + (size_t)m * 16 + nf * 8 + qc * 2) =
                make_float2(acc[nf][2 * h], acc[nf][2 * h + 1]);
    }
}

// ---------------- fused aggregation + finalize: one warp per dst node, 4-way MLP gather ----------------
__global__ __launch_bounds__(256) void fused_agg(const float* __restrict__ bl1,
                                                 const float* __restrict__ bla) {
    int w = (blockIdx.x * 256 + threadIdx.x) >> 5;
    if (w >= N_NODES) return;
    int lane = threadIdx.x & 31;
    int start = d_off[w], deg = d_deg[w];
    float4 a0 = make_float4(0.f, 0.f, 0.f, 0.f);
    float4 a1 = make_float4(0.f, 0.f, 0.f, 0.f);
    float acca = 0.f;
    int j = 0;
    for (; j + 4 <= deg; j += 4) {
        int s0 = d_srcs[start + j],     s1 = d_srcs[start + j + 1];
        int s2 = d_srcs[start + j + 2], s3 = d_srcs[start + j + 3];
        const float4* y0 = reinterpret_cast<const float4*>(d_Yl1 + (size_t)s0 * HID);
        const float4* y1 = reinterpret_cast<const float4*>(d_Yl1 + (size_t)s1 * HID);
        const float4* y2 = reinterpret_cast<const float4*>(d_Yl1 + (size_t)s2 * HID);
        const float4* y3 = reinterpret_cast<const float4*>(d_Yl1 + (size_t)s3 * HID);
        float4 v00 = y0[lane], v01 = y0[lane + 32];
        float4 v10 = y1[lane], v11 = y1[lane + 32];
        float4 v20 = y2[lane], v21 = y2[lane + 32];
        float4 v30 = y3[lane], v31 = y3[lane + 32];
        a0.x += v00.x + v10.x + v20.x + v30.x;
        a0.y += v00.y + v10.y + v20.y + v30.y;
        a0.z += v00.z + v10.z + v20.z + v30.z;
        a0.w += v00.w + v10.w + v20.w + v30.w;
        a1.x += v01.x + v11.x + v21.x + v31.x;
        a1.y += v01.y + v11.y + v21.y + v31.y;
        a1.z += v01.z + v11.z + v21.z + v31.z;
        a1.w += v01.w + v11.w + v21.w + v31.w;
        if (lane < 8)
            acca += d_Ya[s0 * 16 + lane] + d_Ya[s1 * 16 + lane]
                  + d_Ya[s2 * 16 + lane] + d_Ya[s3 * 16 + lane];
    }
    for (; j < deg; j++) {
        int s = d_srcs[start + j];
        const float4* ys = reinterpret_cast<const float4*>(d_Yl1 + (size_t)s * HID);
        float4 v0 = ys[lane], v1 = ys[lane + 32];
        a0.x += v0.x; a0.y += v0.y; a0.z += v0.z; a0.w += v0.w;
        a1.x += v1.x; a1.y += v1.y; a1.z += v1.z; a1.w += v1.w;
        if (lane < 8) acca += d_Ya[s * 16 + lane];
    }
    float inv = (deg > 0) ? 1.f / (float)deg : 0.f;
    const float4* yr = reinterpret_cast<const float4*>(d_Yr1 + (size_t)w * HID);
    const float4* bp = reinterpret_cast<const float4*>(bl1);
    float4 r0 = yr[lane], r1 = yr[lane + 32];
    float4 b0 = bp[lane], b1 = bp[lane + 32];
    float4 z0, z1;
    z0.x = fmaxf(a0.x * inv + b0.x + r0.x, 0.f);
    z0.y = fmaxf(a0.y * inv + b0.y + r0.y, 0.f);
    z0.z = fmaxf(a0.z * inv + b0.z + r0.z, 0.f);
    z0.w = fmaxf(a0.w * inv + b0.w + r0.w, 0.f);
    z1.x = fmaxf(a1.x * inv + b1.x + r1.x, 0.f);
    z1.y = fmaxf(a1.y * inv + b1.y + r1.y, 0.f);
    z1.z = fmaxf(a1.z * inv + b1.z + r1.z, 0.f);
    z1.w = fmaxf(a1.w * inv + b1.w + r1.w, 0.f);
    float4* zp = reinterpret_cast<float4*>(d_Z + (size_t)w * HID);
    zp[lane] = z0; zp[lane + 32] = z1;

    float sv = -1e30f;
    if (lane < 8) sv = acca * inv + bla[lane] + d_Ya[w * 16 + 8 + lane];
    float mx = sv;
    mx = fmaxf(mx, __shfl_xor_sync(0xffffffffu, mx, 4));
    mx = fmaxf(mx, __shfl_xor_sync(0xffffffffu, mx, 2));
    mx = fmaxf(mx, __shfl_xor_sync(0xffffffffu, mx, 1));
    float e = (lane < 8) ? expf(sv - mx) : 0.f;
    float ssum = e;
    ssum += __shfl_xor_sync(0xffffffffu, ssum, 4);
    ssum += __shfl_xor_sync(0xffffffffu, ssum, 2);
    ssum += __shfl_xor_sync(0xffffffffu, ssum, 1);
    if (lane < 8) d_Ss[w * NC + lane] = e / ssum;
}

// ---------------- Xp ----------------
__global__ __launch_bounds__(256) void xp_kernel() {
    int g = blockIdx.x >> 2, chunk = blockIdx.x & 3, tid = threadIdx.x;
    float acc[8];
#pragma unroll
    for (int c = 0; c < 8; c++) acc[c] = 0.f;
    int n0 = g * NPG + chunk * 250;
    for (int n = n0; n < n0 + 250; n++) {
        const float4* sp = reinterpret_cast<const float4*>(&d_Ss[n * NC]);
        float4 v0 = sp[0], v1 = sp[1];
        float z = d_Z[(size_t)n * HID + tid];
        acc[0] += v0.x * z; acc[1] += v0.y * z; acc[2] += v0.z * z; acc[3] += v0.w * z;
        acc[4] += v1.x * z; acc[5] += v1.y * z; acc[6] += v1.z * z; acc[7] += v1.w * z;
    }
#pragma unroll
    for (int c = 0; c < 8; c++)
        atomicAdd(&d_Xp[g * (NC * HID) + c * HID + tid], acc[c]);
}

// ---------------- Ap ----------------
__global__ __launch_bounds__(128) void ap_kernel(const int* __restrict__ src,
                                                 const int* __restrict__ dst) {
    __shared__ float apl[4 * NUM_GRAPHS * 64];
    int tid = threadIdx.x, wid = tid >> 5, lane = tid & 31;
    for (int i = tid; i < 4 * NUM_GRAPHS * 64; i += 128) apl[i] = 0.f;
    __syncthreads();
    float* my = apl + wid * (NUM_GRAPHS * 64);
    int gw = blockIdx.x * 4 + wid;
#pragma unroll
    for (int b = 0; b < 2; b++) {
        int e = gw * 64 + b * 32 + lane;
        int s = src[e], d = dst[e];
        for (int j = 0; j < 32; j++) {
            int sj = __shfl_sync(0xffffffffu, s, j);
            int dj = __shfl_sync(0xffffffffu, d, j);
            int gj = sj / NPG;
            float v = 0.f;
            if (lane < 8)       v = d_Ss[sj * NC + lane];
            else if (lane < 16) v = d_Ss[dj * NC + (lane - 8)];
            int a1 = lane >> 3;
            int bb = lane & 7;
            float s1 = __shfl_sync(0xffffffffu, v, a1);
            float s2 = __shfl_sync(0xffffffffu, v, a1 + 4);
            float sd = __shfl_sync(0xffffffffu, v, 8 + bb);
            float* p = my + gj * 64;
            p[lane]      += s1 * sd;
            p[lane + 32] += s2 * sd;
        }
    }
    __syncthreads();
    for (int i = tid; i < NUM_GRAPHS * 64; i += 128) {
        float a = apl[i] + apl[NUM_GRAPHS * 64 + i] +
                  apl[2 * NUM_GRAPHS * 64 + i] + apl[3 * NUM_GRAPHS * 64 + i];
        atomicAdd(&d_Ap[i], a);
    }
}

// ---------------- pooled conv + classifier ----------------
__global__ __launch_bounds__(256) void final_kernel(const float* __restrict__ Wl2,
                                                    const float* __restrict__ bl2,
                                                    const float* __restrict__ Wr2,
                                                    const float* __restrict__ Wc1,
                                                    const float* __restrict__ bc1,
                                                    const float* __restrict__ Wc2,
                                                    const float* __restrict__ bc2,
                                                    float* __restrict__ out) {
    int g = blockIdx.x, tid = threadIdx.x;
    __shared__ float maskS[64];
    __shared__ float degS[8];
    __shared__ float xps[8 * 256];
    __shared__ float a2s[8 * 256];
    __shared__ float zps[2048];
    __shared__ float red[256];

    if (tid < 64) maskS[tid] = (d_Ap[g * 64 + tid] != 0.0f) ? 1.0f : 0.0f;
    __syncthreads();
    if (tid < 8) {
        float dg = 0.f;
#pragma unroll
        for (int i = 0; i < 8; i++) dg += maskS[i * 8 + tid];
        degS[tid] = dg;
    }
#pragma unroll
    for (int c = 0; c < 8; c++)
        xps[c * 256 + tid] = d_Xp[g * 2048 + c * 256 + tid];
    __syncthreads();

#pragma unroll
    for (int j = 0; j < 8; j++) {
        float s = 0.f;
#pragma unroll
        for (int i = 0; i < 8; i++) s += maskS[i * 8 + j] * xps[i * 256 + tid];
        float dg = degS[j];
        a2s[j * 256 + tid] = (dg > 0.f) ? s / fmaxf(dg, 1.f) : 0.f;
    }
    __syncthreads();

    float acc[8];
    float bb = bl2[tid];
#pragma unroll
    for (int j = 0; j < 8; j++) acc[j] = bb;
    for (int k = 0; k < 256; k++) {
        float wl = Wl2[k * 256 + tid];
        float wr = Wr2[k * 256 + tid];
#pragma unroll
        for (int j = 0; j < 8; j++)
            acc[j] += a2s[j * 256 + k] * wl + xps[j * 256 + k] * wr;
    }
#pragma unroll
    for (int j = 0; j < 8; j++) zps[j * 256 + tid] = fmaxf(acc[j], 0.f);
    __syncthreads();

    float hacc = bc1[tid];
#pragma unroll 8
    for (int m = 0; m < 2048; m++) hacc += zps[m] * Wc1[m * 256 + tid];
    float hv = fmaxf(hacc, 0.f);
    red[tid] = hv * Wc2[tid];
    __syncthreads();
    for (int s = 128; s > 0; s >>= 1) {
        if (tid < s) red[tid] += red[tid + s];
        __syncthreads();
    }
    if (tid == 0) out[g] = red[0] + bc2[0];
}

// ---------------- launch ----------------
extern "C" void kernel_launch(void* const* d_in, const int* in_sizes, int n_in,
                              void* d_out, int out_size) {
    const float* x   = (const float*)d_in[0];
    const int*   ei  = (const int*)d_in[1];
    const int*   src = ei;
    const int*   dst = ei + N_EDGES;
    const float* Wl1 = (const float*)d_in[3];
    const float* bl1 = (const float*)d_in[4];
    const float* Wr1 = (const float*)d_in[5];
    const float* Wla = (const float*)d_in[6];
    const float* bla = (const float*)d_in[7];
    const float* Wra = (const float*)d_in[8];
    const float* Wl2 = (const float*)d_in[9];
    const float* bl2 = (const float*)d_in[10];
    const float* Wr2 = (const float*)d_in[11];
    const float* Wc1 = (const float*)d_in[12];
    const float* bc1 = (const float*)d_in[13];
    const float* Wc2 = (const float*)d_in[14];
    const float* bc2 = (const float*)d_in[15];
    float* out = (float*)d_out;

    cudaFuncSetAttribute(mma_gemm, cudaFuncAttributeMaxDynamicSharedMemorySize, GEMM_SMEM);

    // mma_gemm 4th -> ncu capture window
    prep_bt<<<17, 256>>>(Wl1, Wr1, Wla, Wra);
    cvt_x_hist<<<2048, 256>>>(x, dst);
    scan_kernel<<<32, 256>>>();
    mma_gemm<<<NWORKERS, 256, GEMM_SMEM>>>();
    ya_gemm<<<250, 256>>>();
    scatter_kernel<<<256, 256>>>(src, dst);
    fused_agg<<<4000, 256>>>(bl1, bla);
    xp_kernel<<<128, 256>>>();
    ap_kernel<<<1000, 128>>>(src, dst);
    final_kernel<<<32, 256>>>(Wl2, bl2, Wr2, Wc1, bc1, Wc2, bc2, out);
}

// round 16
// speedup vs baseline: 1.2031x; 1.2031x over previous
#include <cuda_runtime.h>
#include <cuda_bf16.h>
#include <cstdint>

// ---------------- problem constants ----------------
#define N_NODES   32000
#define NUM_GRAPHS 32
#define NPG       1000
#define N_EDGES   256000
#define IN_DIM    1024
#define HID       256
#define NC        8

// ---------------- scratch (device globals) ----------------
__device__ float d_Yl1 [N_NODES * HID];
__device__ float d_Yr1 [N_NODES * HID];
__device__ float d_Ya  [N_NODES * 16];
__device__ float d_Z   [N_NODES * HID];
__device__ float d_Ss  [N_NODES * NC];
__device__ float d_Xp  [NUM_GRAPHS * NC * HID];
__device__ float d_Ap  [NUM_GRAPHS * NC * NC];
__device__ float d_Zp  [NUM_GRAPHS * NC * HID];
// tf32-rounded operands
__device__ float d_Xt  [N_NODES * IN_DIM];
__device__ float d_Bt  [528 * 1024];
// CSR for dst-sorted edges
__device__ int d_deg [N_NODES];
__device__ int d_off [N_NODES];
__device__ int d_cur [N_NODES];
__device__ int d_srcs[N_EDGES];

// =============== helpers ===============
static __device__ __forceinline__ uint32_t s2u(const void* p) {
    uint32_t a;
    asm("{ .reg .u64 t; cvta.to.shared.u64 t, %1; cvt.u32.u64 %0, t; }" : "=r"(a) : "l"(p));
    return a;
}
static __device__ __forceinline__ uint32_t f2tf(float f) {
    uint32_t r; asm("cvt.rna.tf32.f32 %0, %1;" : "=r"(r) : "f"(f)); return r;
}
#define LDMX4(r0, r1, r2, r3, addr) \
    asm volatile("ldmatrix.sync.aligned.m8n8.x4.shared.b16 {%0,%1,%2,%3}, [%4];" \
        : "=r"(r0), "=r"(r1), "=r"(r2), "=r"(r3) : "r"(addr))
#define MMATF32(c, a, b) \
    asm volatile("mma.sync.aligned.m16n8k8.row.col.f32.tf32.tf32.f32 " \
        "{%0,%1,%2,%3}, {%4,%5,%6,%7}, {%8,%9}, {%0,%1,%2,%3};" \
        : "+f"((c)[0]), "+f"((c)[1]), "+f"((c)[2]), "+f"((c)[3]) \
        : "r"((a)[0]), "r"((a)[1]), "r"((a)[2]), "r"((a)[3]), "r"((b)[0]), "r"((b)[1]))
#define CP16(dst, src) \
    asm volatile("cp.async.cg.shared.global [%0], [%1], 16;" :: "r"(dst), "l"(src))
#define CPCOMMIT() asm volatile("cp.async.commit_group;" ::: "memory")
#define CPWAIT0()  asm volatile("cp.async.wait_group 0;" ::: "memory")
#define CPWAIT1()  asm volatile("cp.async.wait_group 1;" ::: "memory")

// ---------------- convert X to tf32-rounded fp32 + edge histogram ----------------
__global__ __launch_bounds__(256) void cvt_x_hist(const float* __restrict__ X,
                                                  const int* __restrict__ dst) {
    size_t t = (size_t)blockIdx.x * 256 + threadIdx.x;
    size_t stride = (size_t)gridDim.x * 256;
    const float4* xp = reinterpret_cast<const float4*>(X);
    uint4* op = reinterpret_cast<uint4*>(d_Xt);
    size_t n4 = (size_t)N_NODES * IN_DIM / 4;
    for (size_t i = t; i < n4; i += stride) {
        float4 v = xp[i];
        op[i] = make_uint4(f2tf(v.x), f2tf(v.y), f2tf(v.z), f2tf(v.w));
    }
    for (size_t e = t; e < N_EDGES; e += stride) atomicAdd(&d_deg[dst[e]], 1);
}

// ---------------- weight prep: transpose + tf32 round + accumulator zeroing ----------------
__global__ __launch_bounds__(256) void prep_bt(const float* __restrict__ Wl1,
                                               const float* __restrict__ Wr1,
                                               const float* __restrict__ Wla,
                                               const float* __restrict__ Wra) {
    int b = blockIdx.x, tid = threadIdx.x;
    if (b < 16) {
        __shared__ float tile[64][33];
        const float* W = (b < 8) ? Wl1 : Wr1;
        int ncol0 = (b & 7) * 32;
        int nout0 = (b < 8) ? ncol0 : 256 + ncol0;
        int tk8 = tid >> 5, tn = tid & 31;
        int n = tid >> 3, kq = (tid & 7) * 8;
        for (int k0 = 0; k0 < IN_DIM; k0 += 64) {
#pragma unroll
            for (int j = 0; j < 8; j++)
                tile[tk8 * 8 + j][tn] = W[(size_t)(k0 + tk8 * 8 + j) * 256 + ncol0 + tn];
            __syncthreads();
            uint32_t o[8];
#pragma unroll
            for (int q = 0; q < 8; q++) o[q] = f2tf(tile[kq + q][n]);
            uint4* dstp = reinterpret_cast<uint4*>(d_Bt + (size_t)(nout0 + n) * IN_DIM + k0 + kq);
            dstp[0] = make_uint4(o[0], o[1], o[2], o[3]);
            dstp[1] = make_uint4(o[4], o[5], o[6], o[7]);
            __syncthreads();
        }
    } else {
        uint32_t* bt = reinterpret_cast<uint32_t*>(d_Bt);
        for (int idx = tid; idx < 16 * IN_DIM; idx += 256) {
            int n = idx & 15, k = idx >> 4;
            float w = (n < 8) ? Wla[k * 8 + n] : Wra[k * 8 + (n - 8)];
            bt[(size_t)(512 + n) * IN_DIM + k] = f2tf(w);
        }
    }
    int gt = b * 256 + tid, gstride = 17 * 256;
    for (int i = gt; i < N_NODES; i += gstride) d_deg[i] = 0;
    for (int i = gt; i < NUM_GRAPHS * NC * HID; i += gstride) d_Xp[i] = 0.f;
    for (int i = gt; i < NUM_GRAPHS * NC * NC;  i += gstride) d_Ap[i] = 0.f;
}

// ---------------- CSR scan + scatter ----------------
__global__ __launch_bounds__(256) void scan_kernel() {
    __shared__ int sums[256];
    __shared__ int base_sh;
    int g = blockIdx.x, tid = threadIdx.x;
    int s = 0;
    for (int i = tid; i < g * NPG; i += 256) s += d_deg[i];
    sums[tid] = s;
    __syncthreads();
    for (int st = 128; st > 0; st >>= 1) {
        if (tid < st) sums[tid] += sums[tid + st];
        __syncthreads();
    }
    if (tid == 0) base_sh = sums[0];
    __syncthreads();
    int base = base_sh;
    __syncthreads();
    int v[4], loc = 0;
#pragma unroll
    for (int j = 0; j < 4; j++) {
        int i = tid * 4 + j;
        v[j] = (i < NPG) ? d_deg[g * NPG + i] : 0;
        loc += v[j];
    }
    sums[tid] = loc;
    __syncthreads();
    for (int off = 1; off < 256; off <<= 1) {
        int t2 = (tid >= off) ? sums[tid - off] : 0;
        __syncthreads();
        sums[tid] += t2;
        __syncthreads();
    }
    int excl = base + ((tid == 0) ? 0 : sums[tid - 1]);
#pragma unroll
    for (int j = 0; j < 4; j++) {
        int i = tid * 4 + j;
        if (i < NPG) {
            d_off[g * NPG + i] = excl;
            d_cur[g * NPG + i] = excl;
            excl += v[j];
        }
    }
}

__global__ __launch_bounds__(256) void scatter_kernel(const int* __restrict__ src,
                                                      const int* __restrict__ dst) {
    int t = blockIdx.x * blockDim.x + threadIdx.x;
    int stride = gridDim.x * blockDim.x;
    for (int e = t; e < N_EDGES; e += stride) {
        int pos = atomicAdd(&d_cur[dst[e]], 1);
        d_srcs[pos] = src[e];
    }
}

// ---------------- tf32 GEMM (R12 config): BM=128, BN=128, warp tile 64x32, 2 CTAs/SM ----------------
// grid (4, 250): yt 0/1 -> Wl1 cols 0-127/128-255 ; yt 2/3 -> Wr1 cols 0-127/128-255.
#define PADF 36                             // floats per smem row = 144 B
#define A_SZF (128 * PADF * 4)              // 18432 B
#define OFF_B A_SZF
#define STG (2 * A_SZF)                     // 36864
#define GEMM_SMEM (2 * STG)                 // 73728 -> 2 CTAs/SM

__global__ __launch_bounds__(256, 2) void mma_gemm() {
    extern __shared__ char sm[];
    uint32_t sb = s2u(sm);
    int tid = threadIdx.x, lane = tid & 31, wid = tid >> 5;
    int rb = blockIdx.y * 128, yt = blockIdx.x;

    const char* a_g = (const char*)d_Xt +
        ((size_t)(rb + (tid >> 1)) * IN_DIM + (tid & 1) * 16) * 4;
    const char* b_g = (const char*)d_Bt +
        (((size_t)yt * 128 + (tid >> 1)) * IN_DIM + (tid & 1) * 16) * 4;
    uint32_t rc_sts = (uint32_t)((tid >> 1) * PADF + (tid & 1) * 16) * 4;

    int wm = wid >> 2, wn = wid & 3;
    int jm = lane >> 3, r8 = lane & 7;
    uint32_t a_ldm[4], b_ldm[2];
#pragma unroll
    for (int mf = 0; mf < 4; mf++) {
        int row = wm * 64 + mf * 16 + ((jm & 1) << 3) + r8;
        a_ldm[mf] = (uint32_t)(row * PADF * 4 + (jm >> 1) * 16);
    }
#pragma unroll
    for (int nb = 0; nb < 2; nb++) {
        int row = wn * 32 + nb * 16 + ((jm >> 1) << 3) + r8;
        b_ldm[nb] = (uint32_t)(OFF_B + row * PADF * 4 + (jm & 1) * 16);
    }

    float acc[4][4][4];
#pragma unroll
    for (int i = 0; i < 4; i++)
#pragma unroll
        for (int j = 0; j < 4; j++)
#pragma unroll
            for (int k = 0; k < 4; k++) acc[i][j][k] = 0.f;

#define ISSUE_TILE(t, s) do { \
        uint32_t st_ = sb + (uint32_t)(s) * STG; \
        size_t ko_ = (size_t)(t) * 128; \
        CP16(st_ + rc_sts,        a_g + ko_); \
        CP16(st_ + rc_sts + 16,   a_g + ko_ + 16); \
        CP16(st_ + rc_sts + 32,   a_g + ko_ + 32); \
        CP16(st_ + rc_sts + 48,   a_g + ko_ + 48); \
        CP16(st_ + OFF_B + rc_sts,      b_g + ko_); \
        CP16(st_ + OFF_B + rc_sts + 16, b_g + ko_ + 16); \
        CP16(st_ + OFF_B + rc_sts + 32, b_g + ko_ + 32); \
        CP16(st_ + OFF_B + rc_sts + 48, b_g + ko_ + 48); \
    } while (0)

    ISSUE_TILE(0, 0); CPCOMMIT();

    for (int t = 0; t < 32; t++) {
        if (t < 31) { ISSUE_TILE(t + 1, (t + 1) & 1); CPCOMMIT(); CPWAIT1(); }
        else CPWAIT0();
        __syncthreads();
        uint32_t stb = sb + (uint32_t)(t & 1) * STG;
#pragma unroll
        for (int ks = 0; ks < 4; ks++) {
            uint32_t kb = ks * 32;
            uint32_t af[4][4], bf[2][4];
#pragma unroll
            for (int nb = 0; nb < 2; nb++)
                LDMX4(bf[nb][0], bf[nb][1], bf[nb][2], bf[nb][3], stb + b_ldm[nb] + kb);
#pragma unroll
            for (int mf = 0; mf < 4; mf++)
                LDMX4(af[mf][0], af[mf][1], af[mf][2], af[mf][3], stb + a_ldm[mf] + kb);
#pragma unroll
            for (int mf = 0; mf < 4; mf++)
#pragma unroll
                for (int nb = 0; nb < 2; nb++) {
                    MMATF32(acc[mf][nb * 2 + 0], af[mf], &bf[nb][0]);
                    MMATF32(acc[mf][nb * 2 + 1], af[mf], &bf[nb][2]);
                }
        }
        __syncthreads();
    }
#undef ISSUE_TILE

    float* outp = (yt < 2) ? d_Yl1 : d_Yr1;
    int colb = (yt & 1) * 128 + wn * 32;
    int qr = lane >> 2, qc = lane & 3;
#pragma unroll
    for (int mf = 0; mf < 4; mf++)
#pragma unroll
        for (int h = 0; h < 2; h++) {
            int m = rb + wm * 64 + mf * 16 + qr + 8 * h;
            float* orow = outp + (size_t)m * HID + colb + qc * 2;
#pragma unroll
            for (int nf = 0; nf < 4; nf++)
                *reinterpret_cast<float2*>(orow + nf * 8) =
                    make_float2(acc[mf][nf][2 * h], acc[mf][nf][2 * h + 1]);
        }
}

// ---------------- Ya GEMM: [32000,16] = X @ [Wla|Wra], tf32 ----------------
#define YA_SZ (128 * PADF * 4)              // 18432
#define OFF_YB YA_SZ
#define YSTG (YA_SZ + 16 * PADF * 4)        // 20736

__global__ __launch_bounds__(256) void ya_gemm() {
    __shared__ char sm2[2 * YSTG];
    uint32_t sb = s2u(sm2);
    int tid = threadIdx.x, lane = tid & 31, wid = tid >> 5;
    int rb = blockIdx.x * 128;

    const char* a_g = (const char*)d_Xt +
        ((size_t)(rb + (tid >> 1)) * IN_DIM + (tid & 1) * 16) * 4;
    uint32_t a_sts = (uint32_t)((tid >> 1) * PADF + (tid & 1) * 16) * 4;
    int brow = tid >> 3, bch = tid & 7;
    const char* b_g = (const char*)d_Bt + ((size_t)(512 + brow) * IN_DIM + bch * 4) * 4;
    uint32_t b_sts = OFF_YB + (uint32_t)(brow * PADF + bch * 4) * 4;
    int do_b = (tid < 128);

    int jm = lane >> 3, r8 = lane & 7;
    uint32_t a_ldm = (uint32_t)((wid * 16 + ((jm & 1) << 3) + r8) * PADF * 4 + (jm >> 1) * 16);
    uint32_t b_ldm = (uint32_t)(OFF_YB + (((jm >> 1) << 3) + r8) * PADF * 4 + (jm & 1) * 16);

    float acc[2][4];
#pragma unroll
    for (int i = 0; i < 2; i++)
#pragma unroll
        for (int k = 0; k < 4; k++) acc[i][k] = 0.f;

#define YISSUE(t, s) do { \
        uint32_t st_ = sb + (uint32_t)(s) * YSTG; \
        size_t ko_ = (size_t)(t) * 128; \
        CP16(st_ + a_sts,        a_g + ko_); \
        CP16(st_ + a_sts + 16,   a_g + ko_ + 16); \
        CP16(st_ + a_sts + 32,   a_g + ko_ + 32); \
        CP16(st_ + a_sts + 48,   a_g + ko_ + 48); \
        if (do_b) CP16(st_ + b_sts, b_g + ko_); \
    } while (0)

    YISSUE(0, 0); CPCOMMIT();

    for (int t = 0; t < 32; t++) {
        if (t < 31) { YISSUE(t + 1, (t + 1) & 1); CPCOMMIT(); CPWAIT1(); }
        else CPWAIT0();
        __syncthreads();
        uint32_t stb = sb + (uint32_t)(t & 1) * YSTG;
#pragma unroll
        for (int ks = 0; ks < 4; ks++) {
            uint32_t kb = ks * 32;
            uint32_t af[4], bf4[4];
            LDMX4(bf4[0], bf4[1], bf4[2], bf4[3], stb + b_ldm + kb);
            LDMX4(af[0], af[1], af[2], af[3], stb + a_ldm + kb);
            MMATF32(acc[0], af, &bf4[0]);
            MMATF32(acc[1], af, &bf4[2]);
        }
        __syncthreads();
    }
#undef YISSUE

    int qr = lane >> 2, qc = lane & 3;
#pragma unroll
    for (int h = 0; h < 2; h++) {
        int m = rb + wid * 16 + qr + 8 * h;
#pragma unroll
        for (int nf = 0; nf < 2; nf++)
            *reinterpret_cast<float2*>(d_Ya + (size_t)m * 16 + nf * 8 + qc * 2) =
                make_float2(acc[nf][2 * h], acc[nf][2 * h + 1]);
    }
}

// ---------------- fused aggregation + finalize: one warp per dst node, 4-way MLP gather ----------------
__global__ __launch_bounds__(256) void fused_agg(const float* __restrict__ bl1,
                                                 const float* __restrict__ bla) {
    int w = (blockIdx.x * 256 + threadIdx.x) >> 5;
    if (w >= N_NODES) return;
    int lane = threadIdx.x & 31;
    int start = d_off[w], deg = d_deg[w];
    float4 a0 = make_float4(0.f, 0.f, 0.f, 0.f);
    float4 a1 = make_float4(0.f, 0.f, 0.f, 0.f);
    float acca = 0.f;
    int j = 0;
    for (; j + 4 <= deg; j += 4) {
        int s0 = d_srcs[start + j],     s1 = d_srcs[start + j + 1];
        int s2 = d_srcs[start + j + 2], s3 = d_srcs[start + j + 3];
        const float4* y0 = reinterpret_cast<const float4*>(d_Yl1 + (size_t)s0 * HID);
        const float4* y1 = reinterpret_cast<const float4*>(d_Yl1 + (size_t)s1 * HID);
        const float4* y2 = reinterpret_cast<const float4*>(d_Yl1 + (size_t)s2 * HID);
        const float4* y3 = reinterpret_cast<const float4*>(d_Yl1 + (size_t)s3 * HID);
        float4 v00 = y0[lane], v01 = y0[lane + 32];
        float4 v10 = y1[lane], v11 = y1[lane + 32];
        float4 v20 = y2[lane], v21 = y2[lane + 32];
        float4 v30 = y3[lane], v31 = y3[lane + 32];
        a0.x += v00.x + v10.x + v20.x + v30.x;
        a0.y += v00.y + v10.y + v20.y + v30.y;
        a0.z += v00.z + v10.z + v20.z + v30.z;
        a0.w += v00.w + v10.w + v20.w + v30.w;
        a1.x += v01.x + v11.x + v21.x + v31.x;
        a1.y += v01.y + v11.y + v21.y + v31.y;
        a1.z += v01.z + v11.z + v21.z + v31.z;
        a1.w += v01.w + v11.w + v21.w + v31.w;
        if (lane < 8)
            acca += d_Ya[s0 * 16 + lane] + d_Ya[s1 * 16 + lane]
                  + d_Ya[s2 * 16 + lane] + d_Ya[s3 * 16 + lane];
    }
    for (; j < deg; j++) {
        int s = d_srcs[start + j];
        const float4* ys = reinterpret_cast<const float4*>(d_Yl1 + (size_t)s * HID);
        float4 v0 = ys[lane], v1 = ys[lane + 32];
        a0.x += v0.x; a0.y += v0.y; a0.z += v0.z; a0.w += v0.w;
        a1.x += v1.x; a1.y += v1.y; a1.z += v1.z; a1.w += v1.w;
        if (lane < 8) acca += d_Ya[s * 16 + lane];
    }
    float inv = (deg > 0) ? 1.f / (float)deg : 0.f;
    const float4* yr = reinterpret_cast<const float4*>(d_Yr1 + (size_t)w * HID);
    const float4* bp = reinterpret_cast<const float4*>(bl1);
    float4 r0 = yr[lane], r1 = yr[lane + 32];
    float4 b0 = bp[lane], b1 = bp[lane + 32];
    float4 z0, z1;
    z0.x = fmaxf(a0.x * inv + b0.x + r0.x, 0.f);
    z0.y = fmaxf(a0.y * inv + b0.y + r0.y, 0.f);
    z0.z = fmaxf(a0.z * inv + b0.z + r0.z, 0.f);
    z0.w = fmaxf(a0.w * inv + b0.w + r0.w, 0.f);
    z1.x = fmaxf(a1.x * inv + b1.x + r1.x, 0.f);
    z1.y = fmaxf(a1.y * inv + b1.y + r1.y, 0.f);
    z1.z = fmaxf(a1.z * inv + b1.z + r1.z, 0.f);
    z1.w = fmaxf(a1.w * inv + b1.w + r1.w, 0.f);
    float4* zp = reinterpret_cast<float4*>(d_Z + (size_t)w * HID);
    zp[lane] = z0; zp[lane + 32] = z1;

    float sv = -1e30f;
    if (lane < 8) sv = acca * inv + bla[lane] + d_Ya[w * 16 + 8 + lane];
    float mx = sv;
    mx = fmaxf(mx, __shfl_xor_sync(0xffffffffu, mx, 4));
    mx = fmaxf(mx, __shfl_xor_sync(0xffffffffu, mx, 2));
    mx = fmaxf(mx, __shfl_xor_sync(0xffffffffu, mx, 1));
    float e = (lane < 8) ? expf(sv - mx) : 0.f;
    float ssum = e;
    ssum += __shfl_xor_sync(0xffffffffu, ssum, 4);
    ssum += __shfl_xor_sync(0xffffffffu, ssum, 2);
    ssum += __shfl_xor_sync(0xffffffffu, ssum, 1);
    if (lane < 8) d_Ss[w * NC + lane] = e / ssum;
}

// ---------------- Xp: 256 blocks (8 chunks of 125 nodes per graph) ----------------
__global__ __launch_bounds__(256) void xp_kernel() {
    int g = blockIdx.x >> 3, chunk = blockIdx.x & 7, tid = threadIdx.x;
    float acc[8];
#pragma unroll
    for (int c = 0; c < 8; c++) acc[c] = 0.f;
    int n0 = g * NPG + chunk * 125;
    for (int n = n0; n < n0 + 125; n++) {
        const float4* sp = reinterpret_cast<const float4*>(&d_Ss[n * NC]);
        float4 v0 = sp[0], v1 = sp[1];
        float z = d_Z[(size_t)n * HID + tid];
        acc[0] += v0.x * z; acc[1] += v0.y * z; acc[2] += v0.z * z; acc[3] += v0.w * z;
        acc[4] += v1.x * z; acc[5] += v1.y * z; acc[6] += v1.z * z; acc[7] += v1.w * z;
    }
#pragma unroll
    for (int c = 0; c < 8; c++)
        atomicAdd(&d_Xp[g * (NC * HID) + c * HID + tid], acc[c]);
}

// ---------------- Ap ----------------
__global__ __launch_bounds__(128) void ap_kernel(const int* __restrict__ src,
                                                 const int* __restrict__ dst) {
    __shared__ float apl[4 * NUM_GRAPHS * 64];
    int tid = threadIdx.x, wid = tid >> 5, lane = tid & 31;
    for (int i = tid; i < 4 * NUM_GRAPHS * 64; i += 128) apl[i] = 0.f;
    __syncthreads();
    float* my = apl + wid * (NUM_GRAPHS * 64);
    int gw = blockIdx.x * 4 + wid;
#pragma unroll
    for (int b = 0; b < 2; b++) {
        int e = gw * 64 + b * 32 + lane;
        int s = src[e], d = dst[e];
        for (int j = 0; j < 32; j++) {
            int sj = __shfl_sync(0xffffffffu, s, j);
            int dj = __shfl_sync(0xffffffffu, d, j);
            int gj = sj / NPG;
            float v = 0.f;
            if (lane < 8)       v = d_Ss[sj * NC + lane];
            else if (lane < 16) v = d_Ss[dj * NC + (lane - 8)];
            int a1 = lane >> 3;
            int bb = lane & 7;
            float s1 = __shfl_sync(0xffffffffu, v, a1);
            float s2 = __shfl_sync(0xffffffffu, v, a1 + 4);
            float sd = __shfl_sync(0xffffffffu, v, 8 + bb);
            float* p = my + gj * 64;
            p[lane]      += s1 * sd;
            p[lane + 32] += s2 * sd;
        }
    }
    __syncthreads();
    for (int i = tid; i < NUM_GRAPHS * 64; i += 128) {
        float a = apl[i] + apl[NUM_GRAPHS * 64 + i] +
                  apl[2 * NUM_GRAPHS * 64 + i] + apl[3 * NUM_GRAPHS * 64 + i];
        atomicAdd(&d_Ap[i], a);
    }
}

// ---------------- pooled conv (split for parallelism): grid (32 graphs x 8 clusters) ----------------
__global__ __launch_bounds__(256) void zp_kernel(const float* __restrict__ Wl2,
                                                 const float* __restrict__ bl2,
                                                 const float* __restrict__ Wr2) {
    int g = blockIdx.x >> 3, j = blockIdx.x & 7, tid = threadIdx.x;
    __shared__ float maskS[64];
    __shared__ float a2[256];
    __shared__ float xpj[256];
    if (tid < 64) maskS[tid] = (d_Ap[g * 64 + tid] != 0.0f) ? 1.0f : 0.0f;
    __syncthreads();
    float dg = 0.f, s = 0.f;
#pragma unroll
    for (int i = 0; i < 8; i++) {
        float mij = maskS[i * 8 + j];
        dg += mij;
        s += mij * d_Xp[g * 2048 + i * 256 + tid];
    }
    a2[tid] = (dg > 0.f) ? s / fmaxf(dg, 1.f) : 0.f;
    xpj[tid] = d_Xp[g * 2048 + j * 256 + tid];
    __syncthreads();
    float acc = bl2[tid];
    for (int k = 0; k < 256; k++)
        acc += a2[k] * Wl2[k * 256 + tid] + xpj[k] * Wr2[k * 256 + tid];
    d_Zp[g * 2048 + j * 256 + tid] = fmaxf(acc, 0.f);
}

// ---------------- classifier: grid 32 ----------------
__global__ __launch_bounds__(256) void cls_kernel(const float* __restrict__ Wc1,
                                                  const float* __restrict__ bc1,
                                                  const float* __restrict__ Wc2,
                                                  const float* __restrict__ bc2,
                                                  float* __restrict__ out) {
    int g = blockIdx.x, tid = threadIdx.x;
    __shared__ float zs[2048];
    __shared__ float red[256];
#pragma unroll
    for (int c = 0; c < 8; c++) zs[c * 256 + tid] = d_Zp[g * 2048 + c * 256 + tid];
    __syncthreads();
    float hacc = bc1[tid];
#pragma unroll 8
    for (int m = 0; m < 2048; m++) hacc += zs[m] * Wc1[m * 256 + tid];
    float hv = fmaxf(hacc, 0.f);
    red[tid] = hv * Wc2[tid];
    __syncthreads();
    for (int s = 128; s > 0; s >>= 1) {
        if (tid < s) red[tid] += red[tid + s];
        __syncthreads();
    }
    if (tid == 0) out[g] = red[0] + bc2[0];
}

// ---------------- launch ----------------
extern "C" void kernel_launch(void* const* d_in, const int* in_sizes, int n_in,
                              void* d_out, int out_size) {
    const float* x   = (const float*)d_in[0];
    const int*   ei  = (const int*)d_in[1];
    const int*   src = ei;
    const int*   dst = ei + N_EDGES;
    const float* Wl1 = (const float*)d_in[3];
    const float* bl1 = (const float*)d_in[4];
    const float* Wr1 = (const float*)d_in[5];
    const float* Wla = (const float*)d_in[6];
    const float* bla = (const float*)d_in[7];
    const float* Wra = (const float*)d_in[8];
    const float* Wl2 = (const float*)d_in[9];
    const float* bl2 = (const float*)d_in[10];
    const float* Wr2 = (const float*)d_in[11];
    const float* Wc1 = (const float*)d_in[12];
    const float* bc1 = (const float*)d_in[13];
    const float* Wc2 = (const float*)d_in[14];
    const float* bc2 = (const float*)d_in[15];
    float* out = (float*)d_out;

    cudaFuncSetAttribute(mma_gemm, cudaFuncAttributeMaxDynamicSharedMemorySize, GEMM_SMEM);

    prep_bt<<<17, 256>>>(Wl1, Wr1, Wla, Wra);
    cvt_x_hist<<<2048, 256>>>(x, dst);
    scan_kernel<<<32, 256>>>();
    scatter_kernel<<<256, 256>>>(src, dst);   // 4th -> ncu window
    mma_gemm<<<dim3(4, 250), 256, GEMM_SMEM>>>();
    ya_gemm<<<250, 256>>>();
    fused_agg<<<4000, 256>>>(bl1, bla);
    xp_kernel<<<256, 256>>>();
    ap_kernel<<<1000, 128>>>(src, dst);
    zp_kernel<<<256, 256>>>(Wl2, bl2, Wr2);
    cls_kernel<<<32, 256>>>(Wc1, bc1, Wc2, bc2, out);
}